// round 9
// baseline (speedup 1.0000x reference)
#include <cuda_runtime.h>
#include <cstdint>

// Problem constants
constexpr int NB = 128, NTOPK = 8, NH = 2048, NI = 1408, NE = 16, NF = 2 * NI;
constexpr int NCH1 = NH / 64;   // 32 chunks of K=64
constexpr int NCH2 = NI / 64;   // 22

constexpr int SA  = 68;   // B tile pitch (bytes)
constexpr int SAA = 80;   // A tile pitch (16B-aligned for cp.async)

constexpr int ASZ = 128 * SAA;  // 10240 (A stage)
constexpr int BSZ = 64 * SA;    // 4352  (B stage)
// gemm1 smem: A[2] @0 (20480), Bg[3] @20480 (13056), Bu[3] @33536 (13056) = 46592
// gemm2 smem: A[2] @0 (20480), Bs[3] @20480 (13056) = 33536
constexpr int G1_BG = 20480, G1_BU = 33536, G1_SMEM = 46592;
constexpr int G2_BS = 20480, G2_SMEM = 33536;

// ---------------- scratch (static device globals; no allocation) ----------------
__device__ int8_t   g_xq[(size_t)NB * NH];
__device__ float    g_sx[NB];
__device__ float    g_comb[NB * NE];
__device__ int      g_tok[NE * NB];
__device__ int      g_cnt[NE];
__device__ float    g_act[(size_t)NE * NB * NI];   // [e][slot][i]
__device__ int8_t   g_aq[(size_t)NE * NB * NI];
__device__ unsigned g_s2max[NE * NB];              // [e][slot]
__device__ float    g_s2[NE * NB];

// ---------------- helpers ----------------
__device__ __forceinline__ uint32_t smem_u32(const void* p) {
    uint32_t a;
    asm("{ .reg .u64 t; cvta.to.shared.u64 t, %1; cvt.u32.u64 %0, t; }" : "=r"(a) : "l"(p));
    return a;
}
__device__ __forceinline__ void cp16(void* sdst, const void* gsrc) {
    asm volatile("cp.async.cg.shared.global [%0], [%1], 16;"
                 :: "r"(smem_u32(sdst)), "l"(gsrc) : "memory");
}
__device__ __forceinline__ void cp_commit() {
    asm volatile("cp.async.commit_group;" ::: "memory");
}
template <int N>
__device__ __forceinline__ void cp_wait() {
    asm volatile("cp.async.wait_group %0;" :: "n"(N) : "memory");
}
__device__ __forceinline__ void mma_s8(int& c0, int& c1, int& c2, int& c3,
                                       int a0, int a1, int a2, int a3,
                                       int b0, int b1) {
    asm volatile(
        "mma.sync.aligned.m16n8k32.row.col.s32.s8.s8.s32 "
        "{%0,%1,%2,%3}, {%4,%5,%6,%7}, {%8,%9}, {%0,%1,%2,%3};"
        : "+r"(c0), "+r"(c1), "+r"(c2), "+r"(c3)
        : "r"(a0), "r"(a1), "r"(a2), "r"(a3), "r"(b0), "r"(b1));
}
__device__ __forceinline__ uint32_t pack4(int v0, int v1, int v2, int v3) {
    uint32_t lo = __byte_perm((uint32_t)v0, (uint32_t)v1, 0x0040);
    uint32_t hi = __byte_perm((uint32_t)v2, (uint32_t)v3, 0x0040);
    return __byte_perm(lo, hi, 0x5410);
}
__device__ __forceinline__ void ldB4(const int* wb, int stride, int4* L, int t) {
    const int nblk = (t & 15) << 2, kblk = (t >> 4) << 2;
    const int* gp = wb + (size_t)kblk * stride + nblk;
    #pragma unroll
    for (int i = 0; i < 4; i++) L[i] = *(const int4*)(gp + (size_t)i * stride);
}
__device__ __forceinline__ void packSTS(uint8_t* B, const int4* L, int t) {
    const int nblk = (t & 15) << 2, kblk = (t >> 4) << 2;
    #pragma unroll
    for (int j = 0; j < 4; j++) {
        const int v0 = ((const int*)&L[0])[j], v1 = ((const int*)&L[1])[j];
        const int v2 = ((const int*)&L[2])[j], v3 = ((const int*)&L[3])[j];
        *(uint32_t*)(B + (nblk + j) * SA + kblk) = pack4(v0, v1, v2, v3);
    }
}
__device__ __forceinline__ void cpA_gather(uint8_t* As, const int8_t* base, int rowstride,
                                           int k0, const int* st_tok, int mrows, int t) {
    #pragma unroll
    for (int r = 0; r < 2; r++) {
        const int idx = t + r * 256;
        const int m = idx >> 2, kb = (idx & 3) << 4;
        if (m < mrows)
            cp16(As + m * SAA + kb, base + (size_t)st_tok[m] * rowstride + k0 + kb);
    }
}

// ---------------- kernel 0: quantize x, build comb, zero y / s2max ----------------
__global__ void prep_kernel(const float* __restrict__ x,
                            const int* __restrict__ expert_ids,
                            const float* __restrict__ expert_scales,
                            const int* __restrict__ mask,
                            float* __restrict__ y) {
    const int b = blockIdx.x, t = threadIdx.x;
    __shared__ float red[256];
    const float* xr = x + (size_t)b * NH;
    float am = 0.f;
    for (int i = t; i < NH; i += 256) am = fmaxf(am, fabsf(xr[i]));
    red[t] = am;
    __syncthreads();
    for (int s = 128; s > 0; s >>= 1) {
        if (t < s) red[t] = fmaxf(red[t], red[t + s]);
        __syncthreads();
    }
    const float sx = fmaxf(red[0], 1e-12f) / 127.0f;
    const float inv = 1.0f / sx;
    if (t == 0) g_sx[b] = sx;
    for (int i = t; i < NH; i += 256) {
        float v = fminf(fmaxf(xr[i] * inv, -128.f), 127.f);
        g_xq[(size_t)b * NH + i] = (int8_t)(int)rintf(v);
        y[(size_t)b * NH + i] = 0.f;
    }
    if (t < NE) g_s2max[t * NB + b] = 0u;
    if (t == 0) {
        float c[NE];
        #pragma unroll
        for (int e = 0; e < NE; e++) c[e] = 0.f;
        for (int k = 0; k < NTOPK; k++)
            c[expert_ids[b * NTOPK + k]] += expert_scales[b * NTOPK + k];
        const float mk = mask[b] ? 1.f : 0.f;
        #pragma unroll
        for (int e = 0; e < NE; e++) g_comb[b * NE + e] = c[e] * mk;
    }
}

// ---------------- kernel 0b: per-expert token compaction (deterministic) ----------------
__global__ void route_kernel() {    // grid NE, block 128
    const int e = blockIdx.x, t = threadIdx.x;
    const int lane = t & 31, wr = t >> 5;
    const bool act = g_comb[t * NE + e] != 0.f;
    const unsigned bal = __ballot_sync(0xffffffffu, act);
    __shared__ int wcnt[4];
    if (lane == 31) wcnt[wr] = __popc(bal);
    __syncthreads();
    int base = 0;
    for (int i = 0; i < wr; i++) base += wcnt[i];
    if (act)
        g_tok[e * NB + base + __popc(bal & ((1u << lane) - 1u))] = t;
    if (t == 0) g_cnt[e] = wcnt[0] + wcnt[1] + wcnt[2] + wcnt[3];
}

// ---------------- kernel 1: deep-pipelined, token-compacted gemm1 + fused silu ----------------
// grid (NI/64, NE); 256 threads; A double-buffered (cp.async), B triple-buffered (regs+STS)
__global__ void __launch_bounds__(256, 2) gemm1_kernel(
    const int* __restrict__ w1, const float* __restrict__ w1_scale,
    const float* __restrict__ smooth) {
    extern __shared__ uint8_t dsm[];
    __shared__ int st_tok[128];
    __shared__ float scg[64], scu[64], smo[64];

    const int e = blockIdx.y, n0 = blockIdx.x * 64;
    const int t = threadIdx.x, lane = t & 31, w = t >> 5;

    const int cnt = g_cnt[e];
    if (cnt == 0) return;
    const int mt16 = (cnt + 15) >> 4;
    const int mrows = mt16 << 4;

    if (t < 128) st_tok[t] = g_tok[e * NB + min(t, cnt - 1)];
    else if (t < 192) scg[t - 128] = w1_scale[e * NF + n0 + (t - 128)];
    else {
        const int j = t - 192;
        scu[j] = w1_scale[e * NF + NI + n0 + j];
        smo[j] = smooth[e * NI + n0 + j];
    }
    __syncthreads();

    int acc[16][4];
    #pragma unroll
    for (int i = 0; i < 16; i++) { acc[i][0] = 0; acc[i][1] = 0; acc[i][2] = 0; acc[i][3] = 0; }

    const int* w1e = w1 + (size_t)e * NH * NF;

    int4 Lg[4], Lu[4];
    {   // prologue: pack B(0) now; leave B(1) in regs; A(0) via cp.async
        ldB4(w1e + n0, NF, Lg, t);
        ldB4(w1e + NI + n0, NF, Lu, t);
        packSTS(dsm + G1_BG, Lg, t);
        packSTS(dsm + G1_BU, Lu, t);
        const int* wb = w1e + (size_t)64 * NF + n0;
        ldB4(wb, NF, Lg, t);
        ldB4(wb + NI, NF, Lu, t);
        cpA_gather(dsm, g_xq, NH, 0, st_tok, mrows, t);
        cp_commit();
    }

    for (int c = 0; c < NCH1; c++) {
        const int bc = c % 3;                 // B stage for this chunk
        uint8_t* As = dsm + (c & 1) * ASZ;
        uint8_t* Bg = dsm + G1_BG + bc * BSZ;
        uint8_t* Bu = dsm + G1_BU + bc * BSZ;

        cp_wait<0>();                          // A(c) ready
        __syncthreads();                       // all warps past MMA(c-1); stages visible

        if (c + 1 < NCH1) {                    // pack B(c+1): regs issued >=1 chunk ago
            const int bn = (c + 1) % 3;
            packSTS(dsm + G1_BG + bn * BSZ, Lg, t);
            packSTS(dsm + G1_BU + bn * BSZ, Lu, t);
        }
        if (c + 2 < NCH1) {                    // issue B(c+2) loads (2 chunks of slack)
            const int* wb = w1e + (size_t)(c + 2) * 64 * NF + n0;
            ldB4(wb, NF, Lg, t);
            ldB4(wb + NI, NF, Lu, t);
        }
        if (c + 1 < NCH1) {
            cpA_gather(dsm + ((c + 1) & 1) * ASZ, g_xq, NH, (c + 1) * 64, st_tok, mrows, t);
            cp_commit();
        }

        if (w < mt16) {
            #pragma unroll
            for (int ks = 0; ks < 64; ks += 32) {
                const uint8_t* ap = As + (w * 16 + (lane >> 2)) * SAA + ks + (lane & 3) * 4;
                const int a0 = *(const int*)ap;
                const int a1 = *(const int*)(ap + 8 * SAA);
                const int a2 = *(const int*)(ap + 16);
                const int a3 = *(const int*)(ap + 8 * SAA + 16);
                #pragma unroll
                for (int nt = 0; nt < 8; nt++) {
                    const uint8_t* bp = Bg + (nt * 8 + (lane >> 2)) * SA + ks + (lane & 3) * 4;
                    int b0 = *(const int*)bp;
                    int b1 = *(const int*)(bp + 16);
                    mma_s8(acc[nt][0], acc[nt][1], acc[nt][2], acc[nt][3], a0, a1, a2, a3, b0, b1);
                    const uint8_t* up = Bu + (nt * 8 + (lane >> 2)) * SA + ks + (lane & 3) * 4;
                    b0 = *(const int*)up;
                    b1 = *(const int*)(up + 16);
                    mma_s8(acc[8 + nt][0], acc[8 + nt][1], acc[8 + nt][2], acc[8 + nt][3], a0, a1, a2, a3, b0, b1);
                }
            }
        }
    }

    // Epilogue (rows = slots; guard slot < cnt)
    if (w < mt16) {
        const int m0 = w * 16;
        const int r = lane >> 2;
        const int cb = (lane & 3) * 2;
        const int row0 = m0 + r, row1 = m0 + r + 8;
        const float sx0 = g_sx[st_tok[row0]], sx1 = g_sx[st_tok[row1]];
        float amax0 = 0.f, amax1 = 0.f;
        float* actp = g_act + (size_t)e * NB * NI;
        #pragma unroll
        for (int nt = 0; nt < 8; nt++) {
            #pragma unroll
            for (int j = 0; j < 2; j++) {
                const int cn = nt * 8 + cb + j;
                float gv = (float)acc[nt][j] * sx0 * scg[cn];
                float uv = (float)acc[8 + nt][j] * sx0 * scu[cn];
                float av = gv / (1.f + __expf(-gv)) * uv * smo[cn];
                if (row0 < cnt) actp[(size_t)row0 * NI + n0 + cn] = av;
                amax0 = fmaxf(amax0, fabsf(av));
                gv = (float)acc[nt][j + 2] * sx1 * scg[cn];
                uv = (float)acc[8 + nt][j + 2] * sx1 * scu[cn];
                av = gv / (1.f + __expf(-gv)) * uv * smo[cn];
                if (row1 < cnt) actp[(size_t)row1 * NI + n0 + cn] = av;
                amax1 = fmaxf(amax1, fabsf(av));
            }
        }
        amax0 = fmaxf(amax0, __shfl_xor_sync(0xffffffffu, amax0, 1));
        amax0 = fmaxf(amax0, __shfl_xor_sync(0xffffffffu, amax0, 2));
        amax1 = fmaxf(amax1, __shfl_xor_sync(0xffffffffu, amax1, 1));
        amax1 = fmaxf(amax1, __shfl_xor_sync(0xffffffffu, amax1, 2));
        if ((lane & 3) == 0) {
            if (row0 < cnt) atomicMax(&g_s2max[e * NB + row0], __float_as_uint(amax0));
            if (row1 < cnt) atomicMax(&g_s2max[e * NB + row1], __float_as_uint(amax1));
        }
    }
}

// ---------------- kernel 2: quantize act -> aq (active slots only) ----------------
__global__ void quant_kernel() {
    const int eb = blockIdx.x;
    const int e = eb >> 7, slot = eb & 127;
    if (slot >= g_cnt[e]) return;
    const int t = threadIdx.x;
    const float m = __uint_as_float(g_s2max[eb]);
    const float s2 = fmaxf(m, 1e-12f) / 127.0f;
    if (t == 0) g_s2[eb] = s2;
    const float inv = 1.0f / s2;
    const float* ap = g_act + (size_t)eb * NI;
    int8_t* qp = g_aq + (size_t)eb * NI;
    for (int i = t; i < NI; i += 256) {
        float v = fminf(fmaxf(ap[i] * inv, -128.f), 127.f);
        qp[i] = (int8_t)(int)rintf(v);
    }
}

// ---------------- kernel 3: deep-pipelined, token-compacted gemm2 + combine ----------------
// grid (NH/64, NE); 256 threads; A double-buffered, B triple-buffered
__global__ void __launch_bounds__(256, 2) gemm2_kernel(
    const int* __restrict__ w2, const float* __restrict__ w2_scale,
    float* __restrict__ y) {
    extern __shared__ uint8_t dsm[];
    __shared__ int st_tok[128], st_slot[128];
    __shared__ float s2s[128], combs[128], w2ss[64];

    const int e = blockIdx.y, n0 = blockIdx.x * 64;
    const int t = threadIdx.x, lane = t & 31, w = t >> 5;

    const int cnt = g_cnt[e];
    if (cnt == 0) return;
    const int mt16 = (cnt + 15) >> 4;
    const int mrows = mt16 << 4;

    if (t < 128) { st_tok[t] = g_tok[e * NB + min(t, cnt - 1)]; st_slot[t] = min(t, cnt - 1); }
    else if (t < 192) w2ss[t - 128] = w2_scale[e * NH + n0 + (t - 128)];
    __syncthreads();
    if (t < 128) { s2s[t] = g_s2[e * NB + t]; combs[t] = g_comb[st_tok[t] * NE + e]; }

    int acc[8][4];
    #pragma unroll
    for (int i = 0; i < 8; i++) { acc[i][0] = 0; acc[i][1] = 0; acc[i][2] = 0; acc[i][3] = 0; }

    const int8_t* aqe = g_aq + (size_t)e * NB * NI;
    const int* w2e = w2 + (size_t)e * NI * NH;

    int4 L[4];
    {   // prologue
        ldB4(w2e + n0, NH, L, t);
        packSTS(dsm + G2_BS, L, t);
        ldB4(w2e + (size_t)64 * NH + n0, NH, L, t);
        cpA_gather(dsm, aqe, NI, 0, st_slot, mrows, t);
        cp_commit();
    }

    for (int c = 0; c < NCH2; c++) {
        const int bc = c % 3;
        uint8_t* As = dsm + (c & 1) * ASZ;
        uint8_t* Bs = dsm + G2_BS + bc * BSZ;

        cp_wait<0>();
        __syncthreads();

        if (c + 1 < NCH2) packSTS(dsm + G2_BS + ((c + 1) % 3) * BSZ, L, t);
        if (c + 2 < NCH2) ldB4(w2e + (size_t)(c + 2) * 64 * NH + n0, NH, L, t);
        if (c + 1 < NCH2) {
            cpA_gather(dsm + ((c + 1) & 1) * ASZ, aqe, NI, (c + 1) * 64, st_slot, mrows, t);
            cp_commit();
        }

        if (w < mt16) {
            #pragma unroll
            for (int ks = 0; ks < 64; ks += 32) {
                const uint8_t* ap = As + (w * 16 + (lane >> 2)) * SAA + ks + (lane & 3) * 4;
                const int a0 = *(const int*)ap;
                const int a1 = *(const int*)(ap + 8 * SAA);
                const int a2 = *(const int*)(ap + 16);
                const int a3 = *(const int*)(ap + 8 * SAA + 16);
                #pragma unroll
                for (int nt = 0; nt < 8; nt++) {
                    const uint8_t* bp = Bs + (nt * 8 + (lane >> 2)) * SA + ks + (lane & 3) * 4;
                    const int b0 = *(const int*)bp;
                    const int b1 = *(const int*)(bp + 16);
                    mma_s8(acc[nt][0], acc[nt][1], acc[nt][2], acc[nt][3], a0, a1, a2, a3, b0, b1);
                }
            }
        }
    }

    if (w < mt16) {
        const int m0 = w * 16;
        const int r = lane >> 2;
        const int cb = (lane & 3) * 2;
        const int row0 = m0 + r, row1 = m0 + r + 8;
        if (row0 < cnt) {
            const float f0 = s2s[row0] * combs[row0];
            float* yr = y + (size_t)st_tok[row0] * NH + n0;
            #pragma unroll
            for (int nt = 0; nt < 8; nt++)
                #pragma unroll
                for (int j = 0; j < 2; j++) {
                    const int cn = nt * 8 + cb + j;
                    atomicAdd(yr + cn, (float)acc[nt][j] * f0 * w2ss[cn]);
                }
        }
        if (row1 < cnt) {
            const float f1 = s2s[row1] * combs[row1];
            float* yr = y + (size_t)st_tok[row1] * NH + n0;
            #pragma unroll
            for (int nt = 0; nt < 8; nt++)
                #pragma unroll
                for (int j = 0; j < 2; j++) {
                    const int cn = nt * 8 + cb + j;
                    atomicAdd(yr + cn, (float)acc[nt][j + 2] * f1 * w2ss[cn]);
                }
        }
    }
}

// ---------------- entry point ----------------
extern "C" void kernel_launch(void* const* d_in, const int* in_sizes, int n_in,
                              void* d_out, int out_size) {
    const float* x = (const float*)d_in[0];
    const int* expert_ids = (const int*)d_in[1];
    const float* smooth_scales = (const float*)d_in[2];
    const float* expert_scales = (const float*)d_in[3];
    const int* x_active_mask = (const int*)d_in[4];
    const int* w1 = (const int*)d_in[5];
    const float* w1_scale = (const float*)d_in[6];
    const int* w2 = (const int*)d_in[7];
    const float* w2_scale = (const float*)d_in[8];
    float* y = (float*)d_out;

    prep_kernel<<<NB, 256>>>(x, expert_ids, expert_scales, x_active_mask, y);
    route_kernel<<<NE, 128>>>();
    gemm1_kernel<<<dim3(NI / 64, NE), 256, G1_SMEM>>>(w1, w1_scale, smooth_scales);
    quant_kernel<<<NE * NB, 256>>>();
    gemm2_kernel<<<dim3(NH / 64, NE), 256, G2_SMEM>>>(w2, w2_scale, y);
}

// round 10
// speedup vs baseline: 1.1379x; 1.1379x over previous
#include <cuda_runtime.h>
#include <cstdint>

// Problem constants
constexpr int NB = 128, NTOPK = 8, NH = 2048, NI = 1408, NE = 16, NF = 2 * NI;
constexpr int NCH1 = NH / 64;   // 32 chunks of K=64
constexpr int NCH2 = NI / 64;   // 22

constexpr int SA  = 68;   // B tile pitch (bytes)
constexpr int SAA = 80;   // A tile pitch (16B-aligned for cp.async)

constexpr int ASZ  = 128 * SAA; // 10240 (A stage)
constexpr int BSZ  = 64 * SA;   // 4352  (B stage, N=64)
constexpr int BSZ1 = 32 * SA;   // 2176  (B stage, N=32)
// gemm1 smem: A[2] @0 (20480), Bg[2] @20480 (4352), Bu[2] @24832 (4352) = 29184
// gemm2 smem: A[2] @0 (20480), Bs[2] @20480 (8704) = 29184
constexpr int G1_BG = 20480, G1_BU = 24832, G1_SMEM = 29184;
constexpr int G2_BS = 20480, G2_SMEM = 29184;

// ---------------- scratch (static device globals; no allocation) ----------------
__device__ int8_t   g_xq[(size_t)NB * NH];
__device__ float    g_sx[NB];
__device__ float    g_comb[NB * NE];
__device__ int      g_tok[NE * NB];
__device__ int      g_cnt[NE];
__device__ float    g_act[(size_t)NE * NB * NI];   // [e][slot][i]
__device__ int8_t   g_aq[(size_t)NE * NB * NI];
__device__ unsigned g_s2max[NE * NB];              // [e][slot]
__device__ float    g_s2[NE * NB];

// ---------------- helpers ----------------
__device__ __forceinline__ uint32_t smem_u32(const void* p) {
    uint32_t a;
    asm("{ .reg .u64 t; cvta.to.shared.u64 t, %1; cvt.u32.u64 %0, t; }" : "=r"(a) : "l"(p));
    return a;
}
__device__ __forceinline__ void cp16(void* sdst, const void* gsrc) {
    asm volatile("cp.async.cg.shared.global [%0], [%1], 16;"
                 :: "r"(smem_u32(sdst)), "l"(gsrc) : "memory");
}
__device__ __forceinline__ void cp_commit() {
    asm volatile("cp.async.commit_group;" ::: "memory");
}
template <int N>
__device__ __forceinline__ void cp_wait() {
    asm volatile("cp.async.wait_group %0;" :: "n"(N) : "memory");
}
__device__ __forceinline__ void mma_s8(int& c0, int& c1, int& c2, int& c3,
                                       int a0, int a1, int a2, int a3,
                                       int b0, int b1) {
    asm volatile(
        "mma.sync.aligned.m16n8k32.row.col.s32.s8.s8.s32 "
        "{%0,%1,%2,%3}, {%4,%5,%6,%7}, {%8,%9}, {%0,%1,%2,%3};"
        : "+r"(c0), "+r"(c1), "+r"(c2), "+r"(c3)
        : "r"(a0), "r"(a1), "r"(a2), "r"(a3), "r"(b0), "r"(b1));
}
__device__ __forceinline__ uint32_t pack4(int v0, int v1, int v2, int v3) {
    uint32_t lo = __byte_perm((uint32_t)v0, (uint32_t)v1, 0x0040);
    uint32_t hi = __byte_perm((uint32_t)v2, (uint32_t)v3, 0x0040);
    return __byte_perm(lo, hi, 0x5410);
}
// N=64 tile: thread t covers 4n x 4k
__device__ __forceinline__ void ldB4(const int* wb, int stride, int4* L, int t) {
    const int nblk = (t & 15) << 2, kblk = (t >> 4) << 2;
    const int* gp = wb + (size_t)kblk * stride + nblk;
    #pragma unroll
    for (int i = 0; i < 4; i++) L[i] = *(const int4*)(gp + (size_t)i * stride);
}
__device__ __forceinline__ void packSTS(uint8_t* B, const int4* L, int t) {
    const int nblk = (t & 15) << 2, kblk = (t >> 4) << 2;
    #pragma unroll
    for (int j = 0; j < 4; j++) {
        const int v0 = ((const int*)&L[0])[j], v1 = ((const int*)&L[1])[j];
        const int v2 = ((const int*)&L[2])[j], v3 = ((const int*)&L[3])[j];
        *(uint32_t*)(B + (nblk + j) * SA + kblk) = pack4(v0, v1, v2, v3);
    }
}
// N=32 tile, 128 threads (tt in [0,128)): thread covers 4n x 4k
__device__ __forceinline__ void ldB4_32(const int* wb, int stride, int4* L, int tt) {
    const int nblk = (tt & 7) << 2, kblk = (tt >> 3) << 2;
    const int* gp = wb + (size_t)kblk * stride + nblk;
    #pragma unroll
    for (int i = 0; i < 4; i++) L[i] = *(const int4*)(gp + (size_t)i * stride);
}
__device__ __forceinline__ void packSTS_32(uint8_t* B, const int4* L, int tt) {
    const int nblk = (tt & 7) << 2, kblk = (tt >> 3) << 2;
    #pragma unroll
    for (int j = 0; j < 4; j++) {
        const int v0 = ((const int*)&L[0])[j], v1 = ((const int*)&L[1])[j];
        const int v2 = ((const int*)&L[2])[j], v3 = ((const int*)&L[3])[j];
        *(uint32_t*)(B + (nblk + j) * SA + kblk) = pack4(v0, v1, v2, v3);
    }
}
__device__ __forceinline__ void cpA_gather(uint8_t* As, const int8_t* base, int rowstride,
                                           int k0, const int* st_tok, int mrows, int t) {
    #pragma unroll
    for (int r = 0; r < 2; r++) {
        const int idx = t + r * 256;
        const int m = idx >> 2, kb = (idx & 3) << 4;
        if (m < mrows)
            cp16(As + m * SAA + kb, base + (size_t)st_tok[m] * rowstride + k0 + kb);
    }
}

// ---------------- kernel 0: quantize x, build comb, zero y / s2max ----------------
__global__ void prep_kernel(const float* __restrict__ x,
                            const int* __restrict__ expert_ids,
                            const float* __restrict__ expert_scales,
                            const int* __restrict__ mask,
                            float* __restrict__ y) {
    const int b = blockIdx.x, t = threadIdx.x;
    __shared__ float red[256];
    const float* xr = x + (size_t)b * NH;
    float am = 0.f;
    for (int i = t; i < NH; i += 256) am = fmaxf(am, fabsf(xr[i]));
    red[t] = am;
    __syncthreads();
    for (int s = 128; s > 0; s >>= 1) {
        if (t < s) red[t] = fmaxf(red[t], red[t + s]);
        __syncthreads();
    }
    const float sx = fmaxf(red[0], 1e-12f) / 127.0f;
    const float inv = 1.0f / sx;
    if (t == 0) g_sx[b] = sx;
    for (int i = t; i < NH; i += 256) {
        float v = fminf(fmaxf(xr[i] * inv, -128.f), 127.f);
        g_xq[(size_t)b * NH + i] = (int8_t)(int)rintf(v);
        y[(size_t)b * NH + i] = 0.f;
    }
    if (t < NE) g_s2max[t * NB + b] = 0u;
    if (t == 0) {
        float c[NE];
        #pragma unroll
        for (int e = 0; e < NE; e++) c[e] = 0.f;
        for (int k = 0; k < NTOPK; k++)
            c[expert_ids[b * NTOPK + k]] += expert_scales[b * NTOPK + k];
        const float mk = mask[b] ? 1.f : 0.f;
        #pragma unroll
        for (int e = 0; e < NE; e++) g_comb[b * NE + e] = c[e] * mk;
    }
}

// ---------------- kernel 0b: per-expert token compaction (deterministic) ----------------
__global__ void route_kernel() {    // grid NE, block 128
    const int e = blockIdx.x, t = threadIdx.x;
    const int lane = t & 31, wr = t >> 5;
    const bool act = g_comb[t * NE + e] != 0.f;
    const unsigned bal = __ballot_sync(0xffffffffu, act);
    __shared__ int wcnt[4];
    if (lane == 31) wcnt[wr] = __popc(bal);
    __syncthreads();
    int base = 0;
    for (int i = 0; i < wr; i++) base += wcnt[i];
    if (act)
        g_tok[e * NB + base + __popc(bal & ((1u << lane) - 1u))] = t;
    if (t == 0) g_cnt[e] = wcnt[0] + wcnt[1] + wcnt[2] + wcnt[3];
}

// ---------------- kernel 1: pipelined, token-compacted gemm1, N-tile=32 ----------------
// grid (NI/32, NE); 256 threads; double-buffered SMEM (round-8 schedule)
__global__ void __launch_bounds__(256, 2) gemm1_kernel(
    const int* __restrict__ w1, const float* __restrict__ w1_scale,
    const float* __restrict__ smooth) {
    extern __shared__ uint8_t dsm[];
    __shared__ int st_tok[128];
    __shared__ float scg[32], scu[32], smo[32];

    const int e = blockIdx.y, n0 = blockIdx.x * 32;
    const int t = threadIdx.x, lane = t & 31, w = t >> 5;
    const int tt = t & 127;

    const int cnt = g_cnt[e];
    if (cnt == 0) return;
    const int mt16 = (cnt + 15) >> 4;
    const int mrows = mt16 << 4;

    if (t < 128) st_tok[t] = g_tok[e * NB + min(t, cnt - 1)];
    else if (t < 160) scg[t - 128] = w1_scale[e * NF + n0 + (t - 128)];
    else if (t < 192) scu[t - 160] = w1_scale[e * NF + NI + n0 + (t - 160)];
    else if (t < 224) smo[t - 192] = smooth[e * NI + n0 + (t - 192)];
    __syncthreads();

    int acc[8][4];
    #pragma unroll
    for (int i = 0; i < 8; i++) { acc[i][0] = 0; acc[i][1] = 0; acc[i][2] = 0; acc[i][3] = 0; }

    const int* w1e = w1 + (size_t)e * NH * NF;
    const int* wsrc = (t < 128) ? (w1e + n0) : (w1e + NI + n0);   // gate | up half
    uint8_t* bbase = (t < 128) ? (dsm + G1_BG) : (dsm + G1_BU);

    {   // prologue: stage 0
        int4 L[4];
        ldB4_32(wsrc, NF, L, tt);
        packSTS_32(bbase, L, tt);
        cpA_gather(dsm, g_xq, NH, 0, st_tok, mrows, t);
        cp_commit();
    }

    for (int c = 0; c < NCH1; c++) {
        const int cur = c & 1, nxt = cur ^ 1;
        uint8_t* As = dsm + cur * ASZ;
        uint8_t* Bg = dsm + G1_BG + cur * BSZ1;
        uint8_t* Bu = dsm + G1_BU + cur * BSZ1;
        const bool pf = (c + 1 < NCH1);

        int4 L[4];
        if (pf) ldB4_32(wsrc + (size_t)(c + 1) * 64 * NF, NF, L, tt);
        cp_wait<0>();
        __syncthreads();
        if (pf) { cpA_gather(dsm + nxt * ASZ, g_xq, NH, (c + 1) * 64, st_tok, mrows, t); cp_commit(); }

        if (w < mt16) {
            #pragma unroll
            for (int ks = 0; ks < 64; ks += 32) {
                const uint8_t* ap = As + (w * 16 + (lane >> 2)) * SAA + ks + (lane & 3) * 4;
                const int a0 = *(const int*)ap;
                const int a1 = *(const int*)(ap + 8 * SAA);
                const int a2 = *(const int*)(ap + 16);
                const int a3 = *(const int*)(ap + 8 * SAA + 16);
                #pragma unroll
                for (int nt = 0; nt < 4; nt++) {
                    const uint8_t* bp = Bg + (nt * 8 + (lane >> 2)) * SA + ks + (lane & 3) * 4;
                    int b0 = *(const int*)bp;
                    int b1 = *(const int*)(bp + 16);
                    mma_s8(acc[nt][0], acc[nt][1], acc[nt][2], acc[nt][3], a0, a1, a2, a3, b0, b1);
                    const uint8_t* up = Bu + (nt * 8 + (lane >> 2)) * SA + ks + (lane & 3) * 4;
                    b0 = *(const int*)up;
                    b1 = *(const int*)(up + 16);
                    mma_s8(acc[4 + nt][0], acc[4 + nt][1], acc[4 + nt][2], acc[4 + nt][3], a0, a1, a2, a3, b0, b1);
                }
            }
        }
        if (pf) packSTS_32(bbase + nxt * BSZ1, L, tt);
    }

    // Epilogue (rows = slots; guard slot < cnt)
    if (w < mt16) {
        const int m0 = w * 16;
        const int r = lane >> 2;
        const int cb = (lane & 3) * 2;
        const int row0 = m0 + r, row1 = m0 + r + 8;
        const float sx0 = g_sx[st_tok[row0]], sx1 = g_sx[st_tok[row1]];
        float amax0 = 0.f, amax1 = 0.f;
        float* actp = g_act + (size_t)e * NB * NI;
        #pragma unroll
        for (int nt = 0; nt < 4; nt++) {
            #pragma unroll
            for (int j = 0; j < 2; j++) {
                const int cn = nt * 8 + cb + j;
                float gv = (float)acc[nt][j] * sx0 * scg[cn];
                float uv = (float)acc[4 + nt][j] * sx0 * scu[cn];
                float av = gv / (1.f + __expf(-gv)) * uv * smo[cn];
                if (row0 < cnt) actp[(size_t)row0 * NI + n0 + cn] = av;
                amax0 = fmaxf(amax0, fabsf(av));
                gv = (float)acc[nt][j + 2] * sx1 * scg[cn];
                uv = (float)acc[4 + nt][j + 2] * sx1 * scu[cn];
                av = gv / (1.f + __expf(-gv)) * uv * smo[cn];
                if (row1 < cnt) actp[(size_t)row1 * NI + n0 + cn] = av;
                amax1 = fmaxf(amax1, fabsf(av));
            }
        }
        amax0 = fmaxf(amax0, __shfl_xor_sync(0xffffffffu, amax0, 1));
        amax0 = fmaxf(amax0, __shfl_xor_sync(0xffffffffu, amax0, 2));
        amax1 = fmaxf(amax1, __shfl_xor_sync(0xffffffffu, amax1, 1));
        amax1 = fmaxf(amax1, __shfl_xor_sync(0xffffffffu, amax1, 2));
        if ((lane & 3) == 0) {
            if (row0 < cnt) atomicMax(&g_s2max[e * NB + row0], __float_as_uint(amax0));
            if (row1 < cnt) atomicMax(&g_s2max[e * NB + row1], __float_as_uint(amax1));
        }
    }
}

// ---------------- kernel 2: quantize act -> aq (active slots only) ----------------
__global__ void quant_kernel() {
    const int eb = blockIdx.x;
    const int e = eb >> 7, slot = eb & 127;
    if (slot >= g_cnt[e]) return;
    const int t = threadIdx.x;
    const float m = __uint_as_float(g_s2max[eb]);
    const float s2 = fmaxf(m, 1e-12f) / 127.0f;
    if (t == 0) g_s2[eb] = s2;
    const float inv = 1.0f / s2;
    const float* ap = g_act + (size_t)eb * NI;
    int8_t* qp = g_aq + (size_t)eb * NI;
    for (int i = t; i < NI; i += 256) {
        float v = fminf(fmaxf(ap[i] * inv, -128.f), 127.f);
        qp[i] = (int8_t)(int)rintf(v);
    }
}

// ---------------- kernel 3: pipelined, token-compacted gemm2 + combine (round-8) ----------------
// grid (NH/64, NE); 256 threads; double-buffered SMEM
__global__ void __launch_bounds__(256, 2) gemm2_kernel(
    const int* __restrict__ w2, const float* __restrict__ w2_scale,
    float* __restrict__ y) {
    extern __shared__ uint8_t dsm[];
    __shared__ int st_tok[128], st_slot[128];
    __shared__ float s2s[128], combs[128], w2ss[64];

    const int e = blockIdx.y, n0 = blockIdx.x * 64;
    const int t = threadIdx.x, lane = t & 31, w = t >> 5;

    const int cnt = g_cnt[e];
    if (cnt == 0) return;
    const int mt16 = (cnt + 15) >> 4;
    const int mrows = mt16 << 4;

    if (t < 128) { st_tok[t] = g_tok[e * NB + min(t, cnt - 1)]; st_slot[t] = min(t, cnt - 1); }
    else if (t < 192) w2ss[t - 128] = w2_scale[e * NH + n0 + (t - 128)];
    __syncthreads();
    if (t < 128) { s2s[t] = g_s2[e * NB + t]; combs[t] = g_comb[st_tok[t] * NE + e]; }

    int acc[8][4];
    #pragma unroll
    for (int i = 0; i < 8; i++) { acc[i][0] = 0; acc[i][1] = 0; acc[i][2] = 0; acc[i][3] = 0; }

    const int8_t* aqe = g_aq + (size_t)e * NB * NI;
    const int* w2e = w2 + (size_t)e * NI * NH;

    {   // prologue
        int4 L[4];
        ldB4(w2e + n0, NH, L, t);
        packSTS(dsm + G2_BS, L, t);
        cpA_gather(dsm, aqe, NI, 0, st_slot, mrows, t);
        cp_commit();
    }

    for (int c = 0; c < NCH2; c++) {
        const int cur = c & 1, nxt = cur ^ 1;
        uint8_t* As = dsm + cur * ASZ;
        uint8_t* Bs = dsm + G2_BS + cur * BSZ;
        const bool pf = (c + 1 < NCH2);

        int4 L[4];
        if (pf) ldB4(w2e + (size_t)(c + 1) * 64 * NH + n0, NH, L, t);
        cp_wait<0>();
        __syncthreads();
        if (pf) { cpA_gather(dsm + nxt * ASZ, aqe, NI, (c + 1) * 64, st_slot, mrows, t); cp_commit(); }

        if (w < mt16) {
            #pragma unroll
            for (int ks = 0; ks < 64; ks += 32) {
                const uint8_t* ap = As + (w * 16 + (lane >> 2)) * SAA + ks + (lane & 3) * 4;
                const int a0 = *(const int*)ap;
                const int a1 = *(const int*)(ap + 8 * SAA);
                const int a2 = *(const int*)(ap + 16);
                const int a3 = *(const int*)(ap + 8 * SAA + 16);
                #pragma unroll
                for (int nt = 0; nt < 8; nt++) {
                    const uint8_t* bp = Bs + (nt * 8 + (lane >> 2)) * SA + ks + (lane & 3) * 4;
                    const int b0 = *(const int*)bp;
                    const int b1 = *(const int*)(bp + 16);
                    mma_s8(acc[nt][0], acc[nt][1], acc[nt][2], acc[nt][3], a0, a1, a2, a3, b0, b1);
                }
            }
        }
        if (pf) packSTS(dsm + G2_BS + nxt * BSZ, L, t);
    }

    if (w < mt16) {
        const int m0 = w * 16;
        const int r = lane >> 2;
        const int cb = (lane & 3) * 2;
        const int row0 = m0 + r, row1 = m0 + r + 8;
        if (row0 < cnt) {
            const float f0 = s2s[row0] * combs[row0];
            float* yr = y + (size_t)st_tok[row0] * NH + n0;
            #pragma unroll
            for (int nt = 0; nt < 8; nt++)
                #pragma unroll
                for (int j = 0; j < 2; j++) {
                    const int cn = nt * 8 + cb + j;
                    atomicAdd(yr + cn, (float)acc[nt][j] * f0 * w2ss[cn]);
                }
        }
        if (row1 < cnt) {
            const float f1 = s2s[row1] * combs[row1];
            float* yr = y + (size_t)st_tok[row1] * NH + n0;
            #pragma unroll
            for (int nt = 0; nt < 8; nt++)
                #pragma unroll
                for (int j = 0; j < 2; j++) {
                    const int cn = nt * 8 + cb + j;
                    atomicAdd(yr + cn, (float)acc[nt][j + 2] * f1 * w2ss[cn]);
                }
        }
    }
}

// ---------------- entry point ----------------
extern "C" void kernel_launch(void* const* d_in, const int* in_sizes, int n_in,
                              void* d_out, int out_size) {
    const float* x = (const float*)d_in[0];
    const int* expert_ids = (const int*)d_in[1];
    const float* smooth_scales = (const float*)d_in[2];
    const float* expert_scales = (const float*)d_in[3];
    const int* x_active_mask = (const int*)d_in[4];
    const int* w1 = (const int*)d_in[5];
    const float* w1_scale = (const float*)d_in[6];
    const int* w2 = (const int*)d_in[7];
    const float* w2_scale = (const float*)d_in[8];
    float* y = (float*)d_out;

    prep_kernel<<<NB, 256>>>(x, expert_ids, expert_scales, x_active_mask, y);
    route_kernel<<<NE, 128>>>();
    gemm1_kernel<<<dim3(NI / 32, NE), 256, G1_SMEM>>>(w1, w1_scale, smooth_scales);
    quant_kernel<<<NE * NB, 256>>>();
    gemm2_kernel<<<dim3(NH / 64, NE), 256, G2_SMEM>>>(w2, w2_scale, y);
}

// round 15
// speedup vs baseline: 1.1657x; 1.0244x over previous
#include <cuda_runtime.h>
#include <cstdint>

// Problem constants
constexpr int NB = 128, NTOPK = 8, NH = 2048, NI = 1408, NE = 16, NF = 2 * NI;
constexpr int NCH1 = NH / 64;   // 32 chunks of K=64
constexpr int NCH2 = NI / 64;   // 22

constexpr int SA  = 68;   // B tile pitch (bytes)
constexpr int SAA = 80;   // A tile pitch (16B-aligned for cp.async)

constexpr int ASZ  = 128 * SAA; // 10240 (A stage)
constexpr int BSZ1 = 32 * SA;   // 2176  (B stage, N=32)
// gemm1 smem: A[2] @0 (20480), Bg[2] @20480 (4352), Bu[2] @24832 (4352) = 29184
// gemm2 smem: A[2] @0 (20480), Bs[2] @20480 (4352) = 24832
constexpr int G1_BG = 20480, G1_BU = 24832, G1_SMEM = 29184;
constexpr int G2_BS = 20480, G2_SMEM = 24832;

// ---------------- scratch (static device globals; no allocation) ----------------
__device__ int8_t   g_xq[(size_t)NB * NH];
__device__ float    g_sx[NB];
__device__ float    g_comb[NB * NE];
__device__ int      g_tok[NE * NB];
__device__ int      g_cnt[NE];
__device__ float    g_act[(size_t)NE * NB * NI];   // [e][slot][i]
__device__ int8_t   g_aq[(size_t)NE * NB * NI];
__device__ unsigned g_s2max[NE * NB];              // [e][slot]
__device__ float    g_s2[NE * NB];

// ---------------- helpers ----------------
__device__ __forceinline__ uint32_t smem_u32(const void* p) {
    uint32_t a;
    asm("{ .reg .u64 t; cvta.to.shared.u64 t, %1; cvt.u32.u64 %0, t; }" : "=r"(a) : "l"(p));
    return a;
}
__device__ __forceinline__ void cp16(void* sdst, const void* gsrc) {
    asm volatile("cp.async.cg.shared.global [%0], [%1], 16;"
                 :: "r"(smem_u32(sdst)), "l"(gsrc) : "memory");
}
__device__ __forceinline__ void cp_commit() {
    asm volatile("cp.async.commit_group;" ::: "memory");
}
template <int N>
__device__ __forceinline__ void cp_wait() {
    asm volatile("cp.async.wait_group %0;" :: "n"(N) : "memory");
}
__device__ __forceinline__ void mma_s8(int& c0, int& c1, int& c2, int& c3,
                                       int a0, int a1, int a2, int a3,
                                       int b0, int b1) {
    asm volatile(
        "mma.sync.aligned.m16n8k32.row.col.s32.s8.s8.s32 "
        "{%0,%1,%2,%3}, {%4,%5,%6,%7}, {%8,%9}, {%0,%1,%2,%3};"
        : "+r"(c0), "+r"(c1), "+r"(c2), "+r"(c3)
        : "r"(a0), "r"(a1), "r"(a2), "r"(a3), "r"(b0), "r"(b1));
}
__device__ __forceinline__ uint32_t pack4(int v0, int v1, int v2, int v3) {
    uint32_t lo = __byte_perm((uint32_t)v0, (uint32_t)v1, 0x0040);
    uint32_t hi = __byte_perm((uint32_t)v2, (uint32_t)v3, 0x0040);
    return __byte_perm(lo, hi, 0x5410);
}
// N=32 tile, 128 threads (tt in [0,128)): thread covers 4n x 4k
__device__ __forceinline__ void ldB4_32(const int* wb, int stride, int4* L, int tt) {
    const int nblk = (tt & 7) << 2, kblk = (tt >> 3) << 2;
    const int* gp = wb + (size_t)kblk * stride + nblk;
    #pragma unroll
    for (int i = 0; i < 4; i++) L[i] = *(const int4*)(gp + (size_t)i * stride);
}
__device__ __forceinline__ void packSTS_32(uint8_t* B, const int4* L, int tt) {
    const int nblk = (tt & 7) << 2, kblk = (tt >> 3) << 2;
    #pragma unroll
    for (int j = 0; j < 4; j++) {
        const int v0 = ((const int*)&L[0])[j], v1 = ((const int*)&L[1])[j];
        const int v2 = ((const int*)&L[2])[j], v3 = ((const int*)&L[3])[j];
        *(uint32_t*)(B + (nblk + j) * SA + kblk) = pack4(v0, v1, v2, v3);
    }
}
__device__ __forceinline__ void cpA_gather(uint8_t* As, const int8_t* base, int rowstride,
                                           int k0, const int* st_tok, int mrows, int t) {
    #pragma unroll
    for (int r = 0; r < 2; r++) {
        const int idx = t + r * 256;
        const int m = idx >> 2, kb = (idx & 3) << 4;
        if (m < mrows)
            cp16(As + m * SAA + kb, base + (size_t)st_tok[m] * rowstride + k0 + kb);
    }
}

// ---------------- kernel 0: quantize x, build comb, zero y / s2max ----------------
__global__ void prep_kernel(const float* __restrict__ x,
                            const int* __restrict__ expert_ids,
                            const float* __restrict__ expert_scales,
                            const int* __restrict__ mask,
                            float* __restrict__ y) {
    const int b = blockIdx.x, t = threadIdx.x;
    __shared__ float red[256];
    const float* xr = x + (size_t)b * NH;
    float am = 0.f;
    for (int i = t; i < NH; i += 256) am = fmaxf(am, fabsf(xr[i]));
    red[t] = am;
    __syncthreads();
    for (int s = 128; s > 0; s >>= 1) {
        if (t < s) red[t] = fmaxf(red[t], red[t + s]);
        __syncthreads();
    }
    const float sx = fmaxf(red[0], 1e-12f) / 127.0f;
    const float inv = 1.0f / sx;
    if (t == 0) g_sx[b] = sx;
    for (int i = t; i < NH; i += 256) {
        float v = fminf(fmaxf(xr[i] * inv, -128.f), 127.f);
        g_xq[(size_t)b * NH + i] = (int8_t)(int)rintf(v);
        y[(size_t)b * NH + i] = 0.f;
    }
    if (t < NE) g_s2max[t * NB + b] = 0u;
    if (t == 0) {
        float c[NE];
        #pragma unroll
        for (int e = 0; e < NE; e++) c[e] = 0.f;
        for (int k = 0; k < NTOPK; k++)
            c[expert_ids[b * NTOPK + k]] += expert_scales[b * NTOPK + k];
        const float mk = mask[b] ? 1.f : 0.f;
        #pragma unroll
        for (int e = 0; e < NE; e++) g_comb[b * NE + e] = c[e] * mk;
    }
}

// ---------------- kernel 0b: per-expert token compaction (deterministic) ----------------
__global__ void route_kernel() {    // grid NE, block 128
    const int e = blockIdx.x, t = threadIdx.x;
    const int lane = t & 31, wr = t >> 5;
    const bool act = g_comb[t * NE + e] != 0.f;
    const unsigned bal = __ballot_sync(0xffffffffu, act);
    __shared__ int wcnt[4];
    if (lane == 31) wcnt[wr] = __popc(bal);
    __syncthreads();
    int base = 0;
    for (int i = 0; i < wr; i++) base += wcnt[i];
    if (act)
        g_tok[e * NB + base + __popc(bal & ((1u << lane) - 1u))] = t;
    if (t == 0) g_cnt[e] = wcnt[0] + wcnt[1] + wcnt[2] + wcnt[3];
}

// ---------------- kernel 1: pipelined, token-compacted gemm1, N-tile=32 (round-10 proven) ----------------
// grid (NI/32, NE); 256 threads; double-buffered SMEM
__global__ void __launch_bounds__(256, 2) gemm1_kernel(
    const int* __restrict__ w1, const float* __restrict__ w1_scale,
    const float* __restrict__ smooth) {
    extern __shared__ uint8_t dsm[];
    __shared__ int st_tok[128];
    __shared__ float scg[32], scu[32], smo[32];

    const int e = blockIdx.y, n0 = blockIdx.x * 32;
    const int t = threadIdx.x, lane = t & 31, w = t >> 5;
    const int tt = t & 127;

    const int cnt = g_cnt[e];
    if (cnt == 0) return;
    const int mt16 = (cnt + 15) >> 4;
    const int mrows = mt16 << 4;

    if (t < 128) st_tok[t] = g_tok[e * NB + min(t, cnt - 1)];
    else if (t < 160) scg[t - 128] = w1_scale[e * NF + n0 + (t - 128)];
    else if (t < 192) scu[t - 160] = w1_scale[e * NF + NI + n0 + (t - 160)];
    else if (t < 224) smo[t - 192] = smooth[e * NI + n0 + (t - 192)];
    __syncthreads();

    int acc[8][4];
    #pragma unroll
    for (int i = 0; i < 8; i++) { acc[i][0] = 0; acc[i][1] = 0; acc[i][2] = 0; acc[i][3] = 0; }

    const int* w1e = w1 + (size_t)e * NH * NF;
    const int* wsrc = (t < 128) ? (w1e + n0) : (w1e + NI + n0);   // gate | up half
    uint8_t* bbase = (t < 128) ? (dsm + G1_BG) : (dsm + G1_BU);

    {   // prologue: stage 0
        int4 L[4];
        ldB4_32(wsrc, NF, L, tt);
        packSTS_32(bbase, L, tt);
        cpA_gather(dsm, g_xq, NH, 0, st_tok, mrows, t);
        cp_commit();
    }

    for (int c = 0; c < NCH1; c++) {
        const int cur = c & 1, nxt = cur ^ 1;
        uint8_t* As = dsm + cur * ASZ;
        uint8_t* Bg = dsm + G1_BG + cur * BSZ1;
        uint8_t* Bu = dsm + G1_BU + cur * BSZ1;
        const bool pf = (c + 1 < NCH1);

        int4 L[4];
        if (pf) ldB4_32(wsrc + (size_t)(c + 1) * 64 * NF, NF, L, tt);
        cp_wait<0>();
        __syncthreads();
        if (pf) { cpA_gather(dsm + nxt * ASZ, g_xq, NH, (c + 1) * 64, st_tok, mrows, t); cp_commit(); }

        if (w < mt16) {
            #pragma unroll
            for (int ks = 0; ks < 64; ks += 32) {
                const uint8_t* ap = As + (w * 16 + (lane >> 2)) * SAA + ks + (lane & 3) * 4;
                const int a0 = *(const int*)ap;
                const int a1 = *(const int*)(ap + 8 * SAA);
                const int a2 = *(const int*)(ap + 16);
                const int a3 = *(const int*)(ap + 8 * SAA + 16);
                #pragma unroll
                for (int nt = 0; nt < 4; nt++) {
                    const uint8_t* bp = Bg + (nt * 8 + (lane >> 2)) * SA + ks + (lane & 3) * 4;
                    int b0 = *(const int*)bp;
                    int b1 = *(const int*)(bp + 16);
                    mma_s8(acc[nt][0], acc[nt][1], acc[nt][2], acc[nt][3], a0, a1, a2, a3, b0, b1);
                    const uint8_t* up = Bu + (nt * 8 + (lane >> 2)) * SA + ks + (lane & 3) * 4;
                    b0 = *(const int*)up;
                    b1 = *(const int*)(up + 16);
                    mma_s8(acc[4 + nt][0], acc[4 + nt][1], acc[4 + nt][2], acc[4 + nt][3], a0, a1, a2, a3, b0, b1);
                }
            }
        }
        if (pf) packSTS_32(bbase + nxt * BSZ1, L, tt);
    }

    // Epilogue (rows = slots; guard slot < cnt)
    if (w < mt16) {
        const int m0 = w * 16;
        const int r = lane >> 2;
        const int cb = (lane & 3) * 2;
        const int row0 = m0 + r, row1 = m0 + r + 8;
        const float sx0 = g_sx[st_tok[row0]], sx1 = g_sx[st_tok[row1]];
        float amax0 = 0.f, amax1 = 0.f;
        float* actp = g_act + (size_t)e * NB * NI;
        #pragma unroll
        for (int nt = 0; nt < 4; nt++) {
            #pragma unroll
            for (int j = 0; j < 2; j++) {
                const int cn = nt * 8 + cb + j;
                float gv = (float)acc[nt][j] * sx0 * scg[cn];
                float uv = (float)acc[4 + nt][j] * sx0 * scu[cn];
                float av = gv / (1.f + __expf(-gv)) * uv * smo[cn];
                if (row0 < cnt) actp[(size_t)row0 * NI + n0 + cn] = av;
                amax0 = fmaxf(amax0, fabsf(av));
                gv = (float)acc[nt][j + 2] * sx1 * scg[cn];
                uv = (float)acc[4 + nt][j + 2] * sx1 * scu[cn];
                av = gv / (1.f + __expf(-gv)) * uv * smo[cn];
                if (row1 < cnt) actp[(size_t)row1 * NI + n0 + cn] = av;
                amax1 = fmaxf(amax1, fabsf(av));
            }
        }
        amax0 = fmaxf(amax0, __shfl_xor_sync(0xffffffffu, amax0, 1));
        amax0 = fmaxf(amax0, __shfl_xor_sync(0xffffffffu, amax0, 2));
        amax1 = fmaxf(amax1, __shfl_xor_sync(0xffffffffu, amax1, 1));
        amax1 = fmaxf(amax1, __shfl_xor_sync(0xffffffffu, amax1, 2));
        if ((lane & 3) == 0) {
            if (row0 < cnt) atomicMax(&g_s2max[e * NB + row0], __float_as_uint(amax0));
            if (row1 < cnt) atomicMax(&g_s2max[e * NB + row1], __float_as_uint(amax1));
        }
    }
}

// ---------------- kernel 2: quantize act -> aq (active slots only) ----------------
__global__ void quant_kernel() {
    const int eb = blockIdx.x;
    const int e = eb >> 7, slot = eb & 127;
    if (slot >= g_cnt[e]) return;
    const int t = threadIdx.x;
    const float m = __uint_as_float(g_s2max[eb]);
    const float s2 = fmaxf(m, 1e-12f) / 127.0f;
    if (t == 0) g_s2[eb] = s2;
    const float inv = 1.0f / s2;
    const float* ap = g_act + (size_t)eb * NI;
    int8_t* qp = g_aq + (size_t)eb * NI;
    for (int i = t; i < NI; i += 256) {
        float v = fminf(fmaxf(ap[i] * inv, -128.f), 127.f);
        qp[i] = (int8_t)(int)rintf(v);
    }
}

// ---------------- kernel 3: pipelined, token-compacted gemm2, N-tile=32, occ 2 ----------------
// grid (NH/32, NE); 256 threads; double-buffered SMEM
__global__ void __launch_bounds__(256, 2) gemm2_kernel(
    const int* __restrict__ w2, const float* __restrict__ w2_scale,
    float* __restrict__ y) {
    extern __shared__ uint8_t dsm[];
    __shared__ int st_tok[128], st_slot[128];
    __shared__ float s2s[128], combs[128], w2ss[32];

    const int e = blockIdx.y, n0 = blockIdx.x * 32;
    const int t = threadIdx.x, lane = t & 31, w = t >> 5;
    const int tt = t & 127;

    const int cnt = g_cnt[e];
    if (cnt == 0) return;
    const int mt16 = (cnt + 15) >> 4;
    const int mrows = mt16 << 4;

    if (t < 128) { st_tok[t] = g_tok[e * NB + min(t, cnt - 1)]; st_slot[t] = min(t, cnt - 1); }
    else if (t < 160) w2ss[t - 128] = w2_scale[e * NH + n0 + (t - 128)];
    __syncthreads();
    if (t < 128) { s2s[t] = g_s2[e * NB + t]; combs[t] = g_comb[st_tok[t] * NE + e]; }

    int acc[4][4];
    #pragma unroll
    for (int i = 0; i < 4; i++) { acc[i][0] = 0; acc[i][1] = 0; acc[i][2] = 0; acc[i][3] = 0; }

    const int8_t* aqe = g_aq + (size_t)e * NB * NI;
    const int* w2e = w2 + (size_t)e * NI * NH;

    {   // prologue
        int4 L[4];
        if (t < 128) {
            ldB4_32(w2e + n0, NH, L, tt);
            packSTS_32(dsm + G2_BS, L, tt);
        }
        cpA_gather(dsm, aqe, NI, 0, st_slot, mrows, t);
        cp_commit();
    }

    for (int c = 0; c < NCH2; c++) {
        const int cur = c & 1, nxt = cur ^ 1;
        uint8_t* As = dsm + cur * ASZ;
        uint8_t* Bs = dsm + G2_BS + cur * BSZ1;
        const bool pf = (c + 1 < NCH2);

        int4 L[4];
        if (pf && t < 128) ldB4_32(w2e + (size_t)(c + 1) * 64 * NH + n0, NH, L, tt);
        cp_wait<0>();
        __syncthreads();
        if (pf) { cpA_gather(dsm + nxt * ASZ, aqe, NI, (c + 1) * 64, st_slot, mrows, t); cp_commit(); }

        if (w < mt16) {
            #pragma unroll
            for (int ks = 0; ks < 64; ks += 32) {
                const uint8_t* ap = As + (w * 16 + (lane >> 2)) * SAA + ks + (lane & 3) * 4;
                const int a0 = *(const int*)ap;
                const int a1 = *(const int*)(ap + 8 * SAA);
                const int a2 = *(const int*)(ap + 16);
                const int a3 = *(const int*)(ap + 8 * SAA + 16);
                #pragma unroll
                for (int nt = 0; nt < 4; nt++) {
                    const uint8_t* bp = Bs + (nt * 8 + (lane >> 2)) * SA + ks + (lane & 3) * 4;
                    const int b0 = *(const int*)bp;
                    const int b1 = *(const int*)(bp + 16);
                    mma_s8(acc[nt][0], acc[nt][1], acc[nt][2], acc[nt][3], a0, a1, a2, a3, b0, b1);
                }
            }
        }
        if (pf && t < 128) packSTS_32(dsm + G2_BS + nxt * BSZ1, L, tt);
    }

    if (w < mt16) {
        const int m0 = w * 16;
        const int r = lane >> 2;
        const int cb = (lane & 3) * 2;
        const int row0 = m0 + r, row1 = m0 + r + 8;
        if (row0 < cnt) {
            const float f0 = s2s[row0] * combs[row0];
            float* yr = y + (size_t)st_tok[row0] * NH + n0;
            #pragma unroll
            for (int nt = 0; nt < 4; nt++)
                #pragma unroll
                for (int j = 0; j < 2; j++) {
                    const int cn = nt * 8 + cb + j;
                    atomicAdd(yr + cn, (float)acc[nt][j] * f0 * w2ss[cn]);
                }
        }
        if (row1 < cnt) {
            const float f1 = s2s[row1] * combs[row1];
            float* yr = y + (size_t)st_tok[row1] * NH + n0;
            #pragma unroll
            for (int nt = 0; nt < 4; nt++)
                #pragma unroll
                for (int j = 0; j < 2; j++) {
                    const int cn = nt * 8 + cb + j;
                    atomicAdd(yr + cn, (float)acc[nt][j + 2] * f1 * w2ss[cn]);
                }
        }
    }
}

// ---------------- entry point ----------------
extern "C" void kernel_launch(void* const* d_in, const int* in_sizes, int n_in,
                              void* d_out, int out_size) {
    const float* x = (const float*)d_in[0];
    const int* expert_ids = (const int*)d_in[1];
    const float* smooth_scales = (const float*)d_in[2];
    const float* expert_scales = (const float*)d_in[3];
    const int* x_active_mask = (const int*)d_in[4];
    const int* w1 = (const int*)d_in[5];
    const float* w1_scale = (const float*)d_in[6];
    const int* w2 = (const int*)d_in[7];
    const float* w2_scale = (const float*)d_in[8];
    float* y = (float*)d_out;

    prep_kernel<<<NB, 256>>>(x, expert_ids, expert_scales, x_active_mask, y);
    route_kernel<<<NE, 128>>>();
    gemm1_kernel<<<dim3(NI / 32, NE), 256, G1_SMEM>>>(w1, w1_scale, smooth_scales);
    quant_kernel<<<NE * NB, 256>>>();
    gemm2_kernel<<<dim3(NH / 32, NE), 256, G2_SMEM>>>(w2, w2_scale, y);
}